// round 4
// baseline (speedup 1.0000x reference)
#include <cuda_runtime.h>

// CSpace resonator bank = first-order complex IIR, warp-scan formulation.
// out[b, plane, t]: [0:64)=Re fwd, [64:128)=Im fwd, [128:192)=Re bwd, [192:256)=Im bwd.
// eig = kernel[c,1]/kernel[c,0], scale = kernel[c,0] (real).
//
// Three phases (no shared memory anywhere):
//  1) seed_kernel: per (seq, chunk) warp computes chunk end-state from zero init
//     via per-lane decimated Horner (factor eig^128) + weighted butterfly reduce.
//  2) combine_kernel: per sequence, serial affine prefix over 15 chunk seeds
//     (factor eig^3200) -> incoming state per chunk.
//  3) scan_kernel: per (seq, chunk) warp rescans with true incoming state using
//     a Kogge-Stone affine warp scan (constant eig-power factors); lanes map to
//     consecutive time samples -> all LDG/STG are coalesced float4.

#define T_LEN 48000
#define KLEN  24000
#define NCH   15            // chunks per sequence
#define CHUNK 3200          // T_LEN / NCH
#define TILES 25            // CHUNK / 128
#define NSEQ  512           // per direction: 8 batches * 64 channels
#define WPB   8             // warps per block
#define NWARP (NSEQ * NCH)  // 7680 warps per direction
#define NBLK  (NWARP / WPB) // 960 blocks

__device__ float2 g_seed [2][NSEQ][NCH];
__device__ float2 g_state[2][NSEQ][NCH];

__device__ __forceinline__ float2 cmul(float2 a, float2 b) {
    return make_float2(fmaf(a.x, b.x, -(a.y * b.y)),
                       fmaf(a.x, b.y,  a.y * b.x));
}
__device__ __forceinline__ float2 cfma(float2 a, float2 b, float2 c) {   // a*b + c
    return make_float2(fmaf(a.x, b.x, fmaf(-a.y, b.y, c.x)),
                       fmaf(a.x, b.y, fmaf( a.y, b.x, c.y)));
}
__device__ __forceinline__ float2 cpow_int(float2 base, int e) {
    float2 r = make_float2(1.f, 0.f);
    float2 p = base;
    while (e) { if (e & 1) r = cmul(r, p); p = cmul(p, p); e >>= 1; }
    return r;
}

// ---------------------------------------------------------------------------
template<int DIR>
__global__ __launch_bounds__(256) void seed_kernel(
    const float* __restrict__ audio, const float* __restrict__ kre,
    const float* __restrict__ kim)
{
    const int w     = blockIdx.x * WPB + (threadIdx.x >> 5);
    const int lane  = threadIdx.x & 31;
    const int sid   = w / NCH;
    const int chunk = w - sid * NCH;
    const int b = sid >> 6, c = sid & 63;

    const float k0  = kre[(size_t)c * KLEN];
    const float inv = 1.f / k0;
    const float2 E  = make_float2(kre[(size_t)c * KLEN + 1] * inv,
                                  kim[(size_t)c * KLEN + 1] * inv);
    float2 E128 = E;
    #pragma unroll
    for (int q = 0; q < 7; ++q) E128 = cmul(E128, E128);

    const float* x = audio + (size_t)b * T_LEN;
    const int cb = chunk * CHUNK;

    float2 acc = make_float2(0.f, 0.f);
    #pragma unroll 5
    for (int t = 0; t < TILES; ++t) {
        const int addr = DIR ? (T_LEN - 128 - cb - 128 * t + 124 - 4 * lane)
                             : (cb + 128 * t + 4 * lane);
        float4 v = *(const float4*)(x + addr);
        float s0, s1, s2, s3;
        if (DIR) { s0 = v.w; s1 = v.z; s2 = v.y; s3 = v.x; }
        else     { s0 = v.x; s1 = v.y; s2 = v.z; s3 = v.w; }
        // l = ((s0*E + s1)*E + s2)*E + s3  (Horner, s real)
        float lr = fmaf(E.x, s0, s1);
        float li = E.y * s0;
        float nlr = fmaf(E.x, lr, fmaf(-E.y, li, s2));
        float nli = fmaf(E.y, lr, E.x * li);
        lr = fmaf(E.x, nlr, fmaf(-E.y, nli, s3));
        li = fmaf(E.y, nlr, E.x * nli);
        acc = cfma(E128, acc, make_float2(lr, li));
    }
    // y_end = sum_j E^(124-4j) * acc_j, scaled by k0
    const float2 E4 = cmul(cmul(E, E), cmul(E, E));
    const float2 W  = cpow_int(E4, 31 - lane);
    float2 part = cmul(W, acc);
    #pragma unroll
    for (int d = 16; d >= 1; d >>= 1) {
        part.x += __shfl_xor_sync(0xFFFFFFFFu, part.x, d);
        part.y += __shfl_xor_sync(0xFFFFFFFFu, part.y, d);
    }
    if (lane == 0)
        g_seed[DIR][sid][chunk] = make_float2(part.x * k0, part.y * k0);
}

// ---------------------------------------------------------------------------
__global__ void combine_kernel(const float* __restrict__ kre,
                               const float* __restrict__ kim)
{
    const int tid = blockIdx.x * blockDim.x + threadIdx.x;   // 0..1023
    const int dir = tid >> 9, sid = tid & (NSEQ - 1);
    const int c = sid & 63;
    const float k0  = kre[(size_t)c * KLEN];
    const float inv = 1.f / k0;
    const float2 E  = make_float2(kre[(size_t)c * KLEN + 1] * inv,
                                  kim[(size_t)c * KLEN + 1] * inv);
    const float2 Ec = cpow_int(E, CHUNK);   // eig^3200
    float2 st = make_float2(0.f, 0.f);
    #pragma unroll
    for (int k = 0; k < NCH; ++k) {
        g_state[dir][sid][k] = st;
        st = cfma(Ec, st, g_seed[dir][sid][k]);
    }
}

// ---------------------------------------------------------------------------
template<int DIR>
__global__ __launch_bounds__(256) void scan_kernel(
    const float* __restrict__ audio, const float* __restrict__ kre,
    const float* __restrict__ kim, float* __restrict__ out)
{
    const int w     = blockIdx.x * WPB + (threadIdx.x >> 5);
    const int lane  = threadIdx.x & 31;
    const int sid   = w / NCH;
    const int chunk = w - sid * NCH;
    const int b = sid >> 6, c = sid & 63;

    const float k0    = kre[(size_t)c * KLEN];
    const float inv   = 1.f / k0;
    const float scale = k0;
    const float2 E   = make_float2(kre[(size_t)c * KLEN + 1] * inv,
                                   kim[(size_t)c * KLEN + 1] * inv);
    const float2 E2  = cmul(E, E);
    const float2 E3  = cmul(E2, E);
    const float2 E4  = cmul(E2, E2);
    const float2 F2  = cmul(E4, E4);     // eig^8
    const float2 F4  = cmul(F2, F2);     // eig^16
    const float2 F8  = cmul(F4, F4);     // eig^32
    const float2 F16 = cmul(F8, F8);     // eig^64
    const float2 E128= cmul(F16, F16);
    const float2 E4j = cpow_int(E4, lane);  // eig^(4*lane)

    float2 C = g_state[DIR][sid][chunk];

    const float* x = audio + (size_t)b * T_LEN;
    float* out_re = out + ((size_t)b * 256 + (size_t)DIR * 128 + c) * (size_t)T_LEN;
    float* out_im = out_re + (size_t)64 * T_LEN;
    const int cb = chunk * CHUNK;

    for (int t = 0; t < TILES; ++t) {
        const int addr = DIR ? (T_LEN - 128 - cb - 128 * t + 124 - 4 * lane)
                             : (cb + 128 * t + 4 * lane);
        float4 v = *(const float4*)(x + addr);
        float s0, s1, s2, s3;
        if (DIR) { s0 = v.w * scale; s1 = v.z * scale; s2 = v.y * scale; s3 = v.x * scale; }
        else     { s0 = v.x * scale; s1 = v.y * scale; s2 = v.z * scale; s3 = v.w * scale; }

        // local scan of 4 (from zero), keeping all partials
        const float v0r = s0, v0i = 0.f;
        const float v1r = fmaf(E.x, v0r, s1);
        const float v1i = E.y * v0r;
        const float v2r = fmaf(E.x, v1r, fmaf(-E.y, v1i, s2));
        const float v2i = fmaf(E.y, v1r, E.x * v1i);
        const float v3r = fmaf(E.x, v2r, fmaf(-E.y, v2i, s3));
        const float v3i = fmaf(E.y, v2r, E.x * v2i);

        // Kogge-Stone inclusive affine scan across lanes (factors eig^{4d})
        float ir = v3r, ii = v3i;
        float ur, ui;
        ur = __shfl_up_sync(0xFFFFFFFFu, ir, 1);  ui = __shfl_up_sync(0xFFFFFFFFu, ii, 1);
        if (lane >= 1)  { ir = fmaf(E4.x, ur, fmaf(-E4.y, ui, ir));  ii = fmaf(E4.x, ui, fmaf(E4.y, ur, ii)); }
        ur = __shfl_up_sync(0xFFFFFFFFu, ir, 2);  ui = __shfl_up_sync(0xFFFFFFFFu, ii, 2);
        if (lane >= 2)  { ir = fmaf(F2.x, ur, fmaf(-F2.y, ui, ir));  ii = fmaf(F2.x, ui, fmaf(F2.y, ur, ii)); }
        ur = __shfl_up_sync(0xFFFFFFFFu, ir, 4);  ui = __shfl_up_sync(0xFFFFFFFFu, ii, 4);
        if (lane >= 4)  { ir = fmaf(F4.x, ur, fmaf(-F4.y, ui, ir));  ii = fmaf(F4.x, ui, fmaf(F4.y, ur, ii)); }
        ur = __shfl_up_sync(0xFFFFFFFFu, ir, 8);  ui = __shfl_up_sync(0xFFFFFFFFu, ii, 8);
        if (lane >= 8)  { ir = fmaf(F8.x, ur, fmaf(-F8.y, ui, ir));  ii = fmaf(F8.x, ui, fmaf(F8.y, ur, ii)); }
        ur = __shfl_up_sync(0xFFFFFFFFu, ir, 16); ui = __shfl_up_sync(0xFFFFFFFFu, ii, 16);
        if (lane >= 16) { ir = fmaf(F16.x, ur, fmaf(-F16.y, ui, ir)); ii = fmaf(F16.x, ui, fmaf(F16.y, ur, ii)); }

        // exclusive prefix + carry application
        float exr = __shfl_up_sync(0xFFFFFFFFu, ir, 1);
        float exi = __shfl_up_sync(0xFFFFFFFFu, ii, 1);
        if (lane == 0) { exr = 0.f; exi = 0.f; }
        const float pr = fmaf(E4j.x, C.x, fmaf(-E4j.y, C.y, exr));
        const float pi = fmaf(E4j.x, C.y, fmaf( E4j.y, C.x, exi));

        // outputs: o_k = eig^{k+1} * pre + v_k
        const float o0r = fmaf(E.x,  pr, fmaf(-E.y,  pi, v0r));
        const float o0i = fmaf(E.x,  pi, fmaf( E.y,  pr, v0i));
        const float o1r = fmaf(E2.x, pr, fmaf(-E2.y, pi, v1r));
        const float o1i = fmaf(E2.x, pi, fmaf( E2.y, pr, v1i));
        const float o2r = fmaf(E3.x, pr, fmaf(-E3.y, pi, v2r));
        const float o2i = fmaf(E3.x, pi, fmaf( E3.y, pr, v2i));
        const float o3r = fmaf(E4.x, pr, fmaf(-E4.y, pi, v3r));
        const float o3i = fmaf(E4.x, pi, fmaf( E4.y, pr, v3i));

        // carry: C = eig^128 * C + incl_31
        const float c31r = __shfl_sync(0xFFFFFFFFu, ir, 31);
        const float c31i = __shfl_sync(0xFFFFFFFFu, ii, 31);
        const float nCr = fmaf(E128.x, C.x, fmaf(-E128.y, C.y, c31r));
        const float nCi = fmaf(E128.x, C.y, fmaf( E128.y, C.x, c31i));
        C.x = nCr; C.y = nCi;

        float4 wre, wim;
        if (DIR) { wre = make_float4(o3r, o2r, o1r, o0r); wim = make_float4(o3i, o2i, o1i, o0i); }
        else     { wre = make_float4(o0r, o1r, o2r, o3r); wim = make_float4(o0i, o1i, o2i, o3i); }
        *(float4*)(out_re + addr) = wre;
        *(float4*)(out_im + addr) = wim;
    }
}

extern "C" void kernel_launch(void* const* d_in, const int* in_sizes, int n_in,
                              void* d_out, int out_size) {
    const float* audio = (const float*)d_in[0];
    const float* kre   = (const float*)d_in[1];
    const float* kim   = (const float*)d_in[2];
    float* out = (float*)d_out;
    seed_kernel<0><<<NBLK, 256>>>(audio, kre, kim);
    seed_kernel<1><<<NBLK, 256>>>(audio, kre, kim);
    combine_kernel<<<4, 256>>>(kre, kim);
    scan_kernel<0><<<NBLK, 256>>>(audio, kre, kim, out);
    scan_kernel<1><<<NBLK, 256>>>(audio, kre, kim, out);
}

// round 5
// speedup vs baseline: 1.8226x; 1.8226x over previous
#include <cuda_runtime.h>

// CSpace resonator bank = first-order complex IIR, warp-scan formulation.
// out[b, plane, t]: [0:64)=Re fwd, [64:128)=Im fwd, [128:192)=Re bwd, [192:256)=Im bwd.
// eig = kernel[c,1]/kernel[c,0], scale = kernel[c,0] (real).
//
// R5: carry-injected warp scans (incl values are absolute), 2-tile pipelined
// scan (A injected + B carry-free scanned in parallel, then fixed up), both
// directions in one launch (blockIdx.y), streaming stores.

#define T_LEN 48000
#define KLEN  24000
#define NCH   15            // chunks per sequence
#define CHUNK 3200          // T_LEN / NCH
#define TILES 25            // CHUNK / 128
#define NSEQ  512           // per direction: 8 batches * 64 channels
#define WPB   8             // warps per block
#define NBLK  ((NSEQ * NCH) / WPB)   // 960 blocks per direction

__device__ float2 g_seed [2][NSEQ][NCH];
__device__ float2 g_state[2][NSEQ][NCH];

__device__ __forceinline__ float2 cmul(float2 a, float2 b) {
    return make_float2(fmaf(a.x, b.x, -(a.y * b.y)),
                       fmaf(a.x, b.y,  a.y * b.x));
}
__device__ __forceinline__ float2 cfma(float2 a, float2 b, float2 c) {   // a*b + c
    return make_float2(fmaf(a.x, b.x, fmaf(-a.y, b.y, c.x)),
                       fmaf(a.x, b.y, fmaf( a.y, b.x, c.y)));
}
__device__ __forceinline__ float2 cpow_int(float2 base, int e) {
    float2 r = make_float2(1.f, 0.f);
    float2 p = base;
    while (e) { if (e & 1) r = cmul(r, p); p = cmul(p, p); e >>= 1; }
    return r;
}

// ---------------------------------------------------------------------------
__global__ __launch_bounds__(256) void seed_kernel(
    const float* __restrict__ audio, const float* __restrict__ kre,
    const float* __restrict__ kim)
{
    const int w     = blockIdx.x * WPB + (threadIdx.x >> 5);
    const int lane  = threadIdx.x & 31;
    const int rev   = blockIdx.y;
    const int sid   = w / NCH;
    const int chunk = w - sid * NCH;
    const int b = sid >> 6, c = sid & 63;

    const float k0  = kre[(size_t)c * KLEN];
    const float inv = 1.f / k0;
    const float2 E  = make_float2(kre[(size_t)c * KLEN + 1] * inv,
                                  kim[(size_t)c * KLEN + 1] * inv);
    float2 E128 = E;
    #pragma unroll
    for (int q = 0; q < 7; ++q) E128 = cmul(E128, E128);
    const float2 E256 = cmul(E128, E128);

    const float* x = audio + (size_t)b * T_LEN;
    const int cb = chunk * CHUNK;

    auto horner = [&](float4 v) -> float2 {
        float s0, s1, s2, s3;
        if (rev) { s0 = v.w; s1 = v.z; s2 = v.y; s3 = v.x; }
        else     { s0 = v.x; s1 = v.y; s2 = v.z; s3 = v.w; }
        float lr = fmaf(E.x, s0, s1);
        float li = E.y * s0;
        float nlr = fmaf(E.x, lr, fmaf(-E.y, li, s2));
        float nli = fmaf(E.y, lr, E.x * li);
        return make_float2(fmaf(E.x, nlr, fmaf(-E.y, nli, s3)),
                           fmaf(E.y, nlr, E.x * nli));
    };
    auto addr_of = [&](int t) {
        int flow = cb + 128 * t + 4 * lane;
        return rev ? (T_LEN - 4 - flow) : flow;
    };

    float2 acc = make_float2(0.f, 0.f);
    #pragma unroll 3
    for (int p = 0; p < 12; ++p) {
        float4 va = *(const float4*)(x + addr_of(2 * p));
        float4 vb = *(const float4*)(x + addr_of(2 * p + 1));
        float2 L0 = horner(va);
        float2 L1 = horner(vb);
        acc = cfma(E256, acc, cfma(E128, L0, L1));
    }
    {
        float4 va = *(const float4*)(x + addr_of(24));
        acc = cfma(E128, acc, horner(va));
    }
    // y_end = sum_j E^(124-4j) * acc_j, scaled by k0
    const float2 E4 = cmul(cmul(E, E), cmul(E, E));
    const float2 W  = cpow_int(E4, 31 - lane);
    float2 part = cmul(W, acc);
    #pragma unroll
    for (int d = 16; d >= 1; d >>= 1) {
        part.x += __shfl_xor_sync(0xFFFFFFFFu, part.x, d);
        part.y += __shfl_xor_sync(0xFFFFFFFFu, part.y, d);
    }
    if (lane == 0)
        g_seed[rev][sid][chunk] = make_float2(part.x * k0, part.y * k0);
}

// ---------------------------------------------------------------------------
__global__ void combine_kernel(const float* __restrict__ kre,
                               const float* __restrict__ kim)
{
    const int tid = blockIdx.x * blockDim.x + threadIdx.x;   // 0..1023
    const int dir = tid >> 9, sid = tid & (NSEQ - 1);
    const int c = sid & 63;
    const float k0  = kre[(size_t)c * KLEN];
    const float inv = 1.f / k0;
    const float2 E  = make_float2(kre[(size_t)c * KLEN + 1] * inv,
                                  kim[(size_t)c * KLEN + 1] * inv);
    const float2 Ec = cpow_int(E, CHUNK);   // eig^3200
    float2 st = make_float2(0.f, 0.f);
    #pragma unroll
    for (int k = 0; k < NCH; ++k) {
        g_state[dir][sid][k] = st;
        st = cfma(Ec, st, g_seed[dir][sid][k]);
    }
}

// ---------------------------------------------------------------------------
__global__ __launch_bounds__(256) void scan_kernel(
    const float* __restrict__ audio, const float* __restrict__ kre,
    const float* __restrict__ kim, float* __restrict__ out)
{
    const int w     = blockIdx.x * WPB + (threadIdx.x >> 5);
    const int lane  = threadIdx.x & 31;
    const int rev   = blockIdx.y;
    const int sid   = w / NCH;
    const int chunk = w - sid * NCH;
    const int b = sid >> 6, c = sid & 63;

    const float k0    = kre[(size_t)c * KLEN];
    const float inv   = 1.f / k0;
    const float scale = k0;
    const float2 E   = make_float2(kre[(size_t)c * KLEN + 1] * inv,
                                   kim[(size_t)c * KLEN + 1] * inv);
    const float2 E2  = cmul(E, E);
    const float2 E3  = cmul(E2, E);
    const float2 E4  = cmul(E2, E2);
    const float2 F2  = cmul(E4, E4);     // eig^8
    const float2 F4  = cmul(F2, F2);     // eig^16
    const float2 F8  = cmul(F4, F4);     // eig^32
    const float2 F16 = cmul(F8, F8);     // eig^64
    const float2 E128= cmul(F16, F16);
    const float2 E4j = cpow_int(E4, lane);  // eig^(4*lane), for B fixup

    // C: absolute state before this warp's first sample. Meaningful on lane 0
    // (carry injection); loaded by all lanes (uniform address).
    float2 C = g_state[rev][sid][chunk];

    const float* x = audio + (size_t)b * T_LEN;
    float* out_re = out + ((size_t)b * 256 + (size_t)rev * 128 + c) * (size_t)T_LEN;
    float* out_im = out_re + (size_t)64 * T_LEN;
    const int cb = chunk * CHUNK;

    const unsigned FULL = 0xFFFFFFFFu;
    const int srcB = (lane == 0) ? 31 : (lane - 1);

    #define KS_SCAN(ir, ii)                                                              \
    {   float ur, ui;                                                                     \
        ur = __shfl_up_sync(FULL, ir, 1);  ui = __shfl_up_sync(FULL, ii, 1);              \
        if (lane >= 1)  { float t = fmaf(E4.x, ur, fmaf(-E4.y, ui, ir));                  \
                          ii = fmaf(E4.x, ui, fmaf(E4.y, ur, ii)); ir = t; }              \
        ur = __shfl_up_sync(FULL, ir, 2);  ui = __shfl_up_sync(FULL, ii, 2);              \
        if (lane >= 2)  { float t = fmaf(F2.x, ur, fmaf(-F2.y, ui, ir));                  \
                          ii = fmaf(F2.x, ui, fmaf(F2.y, ur, ii)); ir = t; }              \
        ur = __shfl_up_sync(FULL, ir, 4);  ui = __shfl_up_sync(FULL, ii, 4);              \
        if (lane >= 4)  { float t = fmaf(F4.x, ur, fmaf(-F4.y, ui, ir));                  \
                          ii = fmaf(F4.x, ui, fmaf(F4.y, ur, ii)); ir = t; }              \
        ur = __shfl_up_sync(FULL, ir, 8);  ui = __shfl_up_sync(FULL, ii, 8);              \
        if (lane >= 8)  { float t = fmaf(F8.x, ur, fmaf(-F8.y, ui, ir));                  \
                          ii = fmaf(F8.x, ui, fmaf(F8.y, ur, ii)); ir = t; }              \
        ur = __shfl_up_sync(FULL, ir, 16); ui = __shfl_up_sync(FULL, ii, 16);             \
        if (lane >= 16) { float t = fmaf(F16.x, ur, fmaf(-F16.y, ui, ir));                \
                          ii = fmaf(F16.x, ui, fmaf(F16.y, ur, ii)); ir = t; }            \
    }

    // local 4-sample Horner; carry (cr,ci) injected (zero on non-injecting lanes)
    #define LOCAL4(s0,s1,s2,s3, cr,ci, v0r,v0i,v1r,v1i,v2r,v2i,v3r,v3i)                   \
        v0r = fmaf(E.x, cr, fmaf(-E.y, ci, s0));                                          \
        v0i = fmaf(E.y, cr,  E.x * ci);                                                   \
        v1r = fmaf(E.x, v0r, fmaf(-E.y, v0i, s1));                                        \
        v1i = fmaf(E.y, v0r,  E.x * v0i);                                                 \
        v2r = fmaf(E.x, v1r, fmaf(-E.y, v1i, s2));                                        \
        v2i = fmaf(E.y, v1r,  E.x * v1i);                                                 \
        v3r = fmaf(E.x, v2r, fmaf(-E.y, v2i, s3));                                        \
        v3i = fmaf(E.y, v2r,  E.x * v2i);

    #define UNPACK(v, s0,s1,s2,s3)                                                        \
        if (rev) { s0 = v.w * scale; s1 = v.z * scale; s2 = v.y * scale; s3 = v.x * scale;}\
        else     { s0 = v.x * scale; s1 = v.y * scale; s2 = v.z * scale; s3 = v.w * scale;}

    #define EMIT(addr, pr,pi, v0r,v0i,v1r,v1i,v2r,v2i, o3r,o3i)                           \
    {   float a0r = fmaf(E.x,  pr, fmaf(-E.y,  pi, v0r));                                 \
        float a0i = fmaf(E.x,  pi, fmaf( E.y,  pr, v0i));                                 \
        float a1r = fmaf(E2.x, pr, fmaf(-E2.y, pi, v1r));                                 \
        float a1i = fmaf(E2.x, pi, fmaf( E2.y, pr, v1i));                                 \
        float a2r = fmaf(E3.x, pr, fmaf(-E3.y, pi, v2r));                                 \
        float a2i = fmaf(E3.x, pi, fmaf( E3.y, pr, v2i));                                 \
        float4 wre = rev ? make_float4(o3r, a2r, a1r, a0r)                                \
                         : make_float4(a0r, a1r, a2r, o3r);                               \
        float4 wim = rev ? make_float4(o3i, a2i, a1i, a0i)                                \
                         : make_float4(a0i, a1i, a2i, o3i);                               \
        __stcs((float4*)(out_re + (addr)), wre);                                          \
        __stcs((float4*)(out_im + (addr)), wim);                                          \
    }

    #pragma unroll 2
    for (int p = 0; p < TILES / 2; ++p) {
        const int flowA = cb + 256 * p + 4 * lane;
        const int flowB = flowA + 128;
        const int addrA = rev ? (T_LEN - 4 - flowA) : flowA;
        const int addrB = rev ? (T_LEN - 4 - flowB) : flowB;
        float4 va = *(const float4*)(x + addrA);
        float4 vb = *(const float4*)(x + addrB);

        float a0, a1, a2, a3, b0, b1, b2, b3;
        UNPACK(va, a0, a1, a2, a3);
        UNPACK(vb, b0, b1, b2, b3);

        // Tile A: carry-injected local scan
        const float cr = (lane == 0) ? C.x : 0.f;
        const float ci = (lane == 0) ? C.y : 0.f;
        float Av0r,Av0i,Av1r,Av1i,Av2r,Av2i,Av3r,Av3i;
        LOCAL4(a0,a1,a2,a3, cr,ci, Av0r,Av0i,Av1r,Av1i,Av2r,Av2i,Av3r,Av3i);
        // Tile B: carry-free local scan (independent -> ILP)
        float Bv0r,Bv0i,Bv1r,Bv1i,Bv2r,Bv2i,Bv3r,Bv3i;
        LOCAL4(b0,b1,b2,b3, 0.f,0.f, Bv0r,Bv0i,Bv1r,Bv1i,Bv2r,Bv2i,Bv3r,Bv3i);

        float Air = Av3r, Aii = Av3i;   // A inclusive (absolute after injection)
        float Bir = Bv3r, Bii = Bv3i;   // B inclusive (carry-free)
        KS_SCAN(Air, Aii);              // two independent shuffle chains
        KS_SCAN(Bir, Bii);

        // A outputs: pre = incl[lane-1] (absolute), lane0 pre = 0 (v already absolute)
        float Apr = __shfl_up_sync(FULL, Air, 1);
        float Api = __shfl_up_sync(FULL, Aii, 1);
        if (lane == 0) { Apr = 0.f; Api = 0.f; }
        EMIT(addrA, Apr, Api, Av0r,Av0i,Av1r,Av1i,Av2r,Av2i, Air, Aii);

        // C_B = absolute state at end of A = A incl[31], broadcast
        const float CBr = __shfl_sync(FULL, Air, 31);
        const float CBi = __shfl_sync(FULL, Aii, 31);

        // B fixup: pre = E4^lane * C_B + excl;  lane0 slot carries incl[31] for C'
        const float Bxr = __shfl_sync(FULL, Bir, srcB);
        const float Bxi = __shfl_sync(FULL, Bii, srcB);
        float Bpr, Bpi;
        if (lane == 0) { Bpr = CBr; Bpi = CBi; }
        else {
            Bpr = fmaf(E4j.x, CBr, fmaf(-E4j.y, CBi, Bxr));
            Bpi = fmaf(E4j.x, CBi, fmaf( E4j.y, CBr, Bxi));
        }
        float Bo3r = fmaf(E4.x, Bpr, fmaf(-E4.y, Bpi, Bv3r));
        float Bo3i = fmaf(E4.x, Bpi, fmaf( E4.y, Bpr, Bv3i));
        EMIT(addrB, Bpr, Bpi, Bv0r,Bv0i,Bv1r,Bv1i,Bv2r,Bv2i, Bo3r, Bo3i);

        // next carry (lane 0 only): C' = E128 * C_B + B incl[31]
        C.x = fmaf(E128.x, CBr, fmaf(-E128.y, CBi, Bxr));
        C.y = fmaf(E128.x, CBi, fmaf( E128.y, CBr, Bxi));
    }

    // leftover tile 24: carry-injected single
    {
        const int flow = cb + 128 * (TILES - 1) + 4 * lane;
        const int addr = rev ? (T_LEN - 4 - flow) : flow;
        float4 va = *(const float4*)(x + addr);
        float a0, a1, a2, a3;
        UNPACK(va, a0, a1, a2, a3);
        const float cr = (lane == 0) ? C.x : 0.f;
        const float ci = (lane == 0) ? C.y : 0.f;
        float v0r,v0i,v1r,v1i,v2r,v2i,v3r,v3i;
        LOCAL4(a0,a1,a2,a3, cr,ci, v0r,v0i,v1r,v1i,v2r,v2i,v3r,v3i);
        float ir = v3r, ii = v3i;
        KS_SCAN(ir, ii);
        float pr = __shfl_up_sync(FULL, ir, 1);
        float pi = __shfl_up_sync(FULL, ii, 1);
        if (lane == 0) { pr = 0.f; pi = 0.f; }
        EMIT(addr, pr, pi, v0r,v0i,v1r,v1i,v2r,v2i, ir, ii);
    }
}

extern "C" void kernel_launch(void* const* d_in, const int* in_sizes, int n_in,
                              void* d_out, int out_size) {
    const float* audio = (const float*)d_in[0];
    const float* kre   = (const float*)d_in[1];
    const float* kim   = (const float*)d_in[2];
    float* out = (float*)d_out;
    dim3 grid(NBLK, 2);
    seed_kernel<<<grid, 256>>>(audio, kre, kim);
    combine_kernel<<<4, 256>>>(kre, kim);
    scan_kernel<<<grid, 256>>>(audio, kre, kim, out);
}

// round 6
// speedup vs baseline: 2.1532x; 1.1814x over previous
#include <cuda_runtime.h>

// CSpace resonator bank = first-order complex IIR, single-kernel warp-scan.
// out[b, plane, t]: [0:64)=Re fwd, [64:128)=Im fwd, [128:192)=Re bwd, [192:256)=Im bwd.
// eig = kernel[c,1]/kernel[c,0], scale = kernel[c,0] (real).
//
// R6: fused single kernel. Each (seq, chunk) warp computes its incoming carry
// by scanning a per-channel truncated warmup window (|eig|^H <= 1e-6) with a
// shuffle-free decimated Horner + one butterfly reduce, then runs the R5
// 2-tile pipelined carry-injected warp scan. No global scratch, no extra
// launches (seed/combine phases eliminated: ~21 us).

#define T_LEN 48000
#define KLEN  24000
#define NCH   15            // chunks per sequence
#define CHUNK 3200          // T_LEN / NCH
#define TILES 25            // CHUNK / 128
#define NSEQ  512           // per direction: 8 batches * 64 channels
#define WPB   8             // warps per block
#define NBLK  ((NSEQ * NCH) / WPB)   // 960 blocks per direction

__device__ __forceinline__ float2 cmul(float2 a, float2 b) {
    return make_float2(fmaf(a.x, b.x, -(a.y * b.y)),
                       fmaf(a.x, b.y,  a.y * b.x));
}
__device__ __forceinline__ float2 cfma(float2 a, float2 b, float2 c) {   // a*b + c
    return make_float2(fmaf(a.x, b.x, fmaf(-a.y, b.y, c.x)),
                       fmaf(a.x, b.y, fmaf( a.y, b.x, c.y)));
}
__device__ __forceinline__ float2 cpow_int(float2 base, int e) {
    float2 r = make_float2(1.f, 0.f);
    float2 p = base;
    while (e) { if (e & 1) r = cmul(r, p); p = cmul(p, p); e >>= 1; }
    return r;
}

__global__ __launch_bounds__(256) void cspace_kernel(
    const float* __restrict__ audio, const float* __restrict__ kre,
    const float* __restrict__ kim, float* __restrict__ out)
{
    const int w     = blockIdx.x * WPB + (threadIdx.x >> 5);
    const int lane  = threadIdx.x & 31;
    const int rev   = blockIdx.y;
    const int sid   = w / NCH;
    const int chunk = w - sid * NCH;
    const int b = sid >> 6, c = sid & 63;

    const float k0    = kre[(size_t)c * KLEN];
    const float inv   = 1.f / k0;
    const float scale = k0;
    const float2 E   = make_float2(kre[(size_t)c * KLEN + 1] * inv,
                                   kim[(size_t)c * KLEN + 1] * inv);
    const float2 E2  = cmul(E, E);
    const float2 E3  = cmul(E2, E);
    const float2 E4  = cmul(E2, E2);
    const float2 F2  = cmul(E4, E4);     // eig^8
    const float2 F4  = cmul(F2, F2);     // eig^16
    const float2 F8  = cmul(F4, F4);     // eig^32
    const float2 F16 = cmul(F8, F8);     // eig^64
    const float2 E128= cmul(F16, F16);
    const float2 E4j = cpow_int(E4, lane);       // eig^(4*lane)  (B fixup)

    const float* x = audio + (size_t)b * T_LEN;
    float* out_re = out + ((size_t)b * 256 + (size_t)rev * 128 + c) * (size_t)T_LEN;
    float* out_im = out_re + (size_t)64 * T_LEN;
    const int cb = chunk * CHUNK;
    const unsigned FULL = 0xFFFFFFFFu;

    // ---------------- Warmup: truncated-history carry ----------------------
    // W tiles of 128 samples ending at flow position cb. |eig|^(128W) <= 1e-6.
    float2 C = make_float2(0.f, 0.f);
    {
        const float d2 = fmaf(E.x, E.x, E.y * E.y);          // decay^2
        const float Hf = 13.8155f / (-0.5f * __logf(d2));    // samples needed
        int W = (int)(Hf * (1.0f / 128.0f)) + 1;
        const int Wmax = cb >> 7;                            // available history
        if (W > Wmax) W = Wmax;

        if (W > 0) {
            float2 acc = make_float2(0.f, 0.f);
            const int flow0 = cb - 128 * W + 4 * lane;
            for (int t = 0; t < W; ++t) {
                const int flow = flow0 + 128 * t;
                const int addr = rev ? (T_LEN - 4 - flow) : flow;
                float4 v = __ldg((const float4*)(x + addr));
                float s0, s1, s2, s3;
                if (rev) { s0 = v.w; s1 = v.z; s2 = v.y; s3 = v.x; }
                else     { s0 = v.x; s1 = v.y; s2 = v.z; s3 = v.w; }
                // horner over 4 samples (s real)
                float lr = fmaf(E.x, s0, s1);
                float li = E.y * s0;
                float nlr = fmaf(E.x, lr, fmaf(-E.y, li, s2));
                float nli = fmaf(E.y, lr, E.x * li);
                float2 L = make_float2(fmaf(E.x, nlr, fmaf(-E.y, nli, s3)),
                                       fmaf(E.y, nlr, E.x * nli));
                acc = cfma(E128, acc, L);
            }
            // y(cb-1) = sum_j eig^(124-4j) * acc_j, then scale by k0
            const float2 Wj = cpow_int(E4, 31 - lane);
            float2 part = cmul(Wj, acc);
            #pragma unroll
            for (int d = 16; d >= 1; d >>= 1) {
                part.x += __shfl_xor_sync(FULL, part.x, d);
                part.y += __shfl_xor_sync(FULL, part.y, d);
            }
            C = make_float2(part.x * k0, part.y * k0);
        }
    }

    // ---------------- Main scan (R5 two-tile pipelined) ---------------------
    const int srcB = (lane == 0) ? 31 : (lane - 1);

    #define KS_SCAN(ir, ii)                                                              \
    {   float ur, ui;                                                                     \
        ur = __shfl_up_sync(FULL, ir, 1);  ui = __shfl_up_sync(FULL, ii, 1);              \
        if (lane >= 1)  { float t = fmaf(E4.x, ur, fmaf(-E4.y, ui, ir));                  \
                          ii = fmaf(E4.x, ui, fmaf(E4.y, ur, ii)); ir = t; }              \
        ur = __shfl_up_sync(FULL, ir, 2);  ui = __shfl_up_sync(FULL, ii, 2);              \
        if (lane >= 2)  { float t = fmaf(F2.x, ur, fmaf(-F2.y, ui, ir));                  \
                          ii = fmaf(F2.x, ui, fmaf(F2.y, ur, ii)); ir = t; }              \
        ur = __shfl_up_sync(FULL, ir, 4);  ui = __shfl_up_sync(FULL, ii, 4);              \
        if (lane >= 4)  { float t = fmaf(F4.x, ur, fmaf(-F4.y, ui, ir));                  \
                          ii = fmaf(F4.x, ui, fmaf(F4.y, ur, ii)); ir = t; }              \
        ur = __shfl_up_sync(FULL, ir, 8);  ui = __shfl_up_sync(FULL, ii, 8);              \
        if (lane >= 8)  { float t = fmaf(F8.x, ur, fmaf(-F8.y, ui, ir));                  \
                          ii = fmaf(F8.x, ui, fmaf(F8.y, ur, ii)); ir = t; }              \
        ur = __shfl_up_sync(FULL, ir, 16); ui = __shfl_up_sync(FULL, ii, 16);             \
        if (lane >= 16) { float t = fmaf(F16.x, ur, fmaf(-F16.y, ui, ir));                \
                          ii = fmaf(F16.x, ui, fmaf(F16.y, ur, ii)); ir = t; }            \
    }

    #define LOCAL4(s0,s1,s2,s3, cr,ci, v0r,v0i,v1r,v1i,v2r,v2i,v3r,v3i)                   \
        v0r = fmaf(E.x, cr, fmaf(-E.y, ci, s0));                                          \
        v0i = fmaf(E.y, cr,  E.x * ci);                                                   \
        v1r = fmaf(E.x, v0r, fmaf(-E.y, v0i, s1));                                        \
        v1i = fmaf(E.y, v0r,  E.x * v0i);                                                 \
        v2r = fmaf(E.x, v1r, fmaf(-E.y, v1i, s2));                                        \
        v2i = fmaf(E.y, v1r,  E.x * v1i);                                                 \
        v3r = fmaf(E.x, v2r, fmaf(-E.y, v2i, s3));                                        \
        v3i = fmaf(E.y, v2r,  E.x * v2i);

    #define UNPACK(v, s0,s1,s2,s3)                                                        \
        if (rev) { s0 = v.w * scale; s1 = v.z * scale; s2 = v.y * scale; s3 = v.x * scale;}\
        else     { s0 = v.x * scale; s1 = v.y * scale; s2 = v.z * scale; s3 = v.w * scale;}

    #define EMIT(addr, pr,pi, v0r,v0i,v1r,v1i,v2r,v2i, o3r,o3i)                           \
    {   float a0r = fmaf(E.x,  pr, fmaf(-E.y,  pi, v0r));                                 \
        float a0i = fmaf(E.x,  pi, fmaf( E.y,  pr, v0i));                                 \
        float a1r = fmaf(E2.x, pr, fmaf(-E2.y, pi, v1r));                                 \
        float a1i = fmaf(E2.x, pi, fmaf( E2.y, pr, v1i));                                 \
        float a2r = fmaf(E3.x, pr, fmaf(-E3.y, pi, v2r));                                 \
        float a2i = fmaf(E3.x, pi, fmaf( E3.y, pr, v2i));                                 \
        float4 wre = rev ? make_float4(o3r, a2r, a1r, a0r)                                \
                         : make_float4(a0r, a1r, a2r, o3r);                               \
        float4 wim = rev ? make_float4(o3i, a2i, a1i, a0i)                                \
                         : make_float4(a0i, a1i, a2i, o3i);                               \
        __stcs((float4*)(out_re + (addr)), wre);                                          \
        __stcs((float4*)(out_im + (addr)), wim);                                          \
    }

    #pragma unroll 2
    for (int p = 0; p < TILES / 2; ++p) {
        const int flowA = cb + 256 * p + 4 * lane;
        const int flowB = flowA + 128;
        const int addrA = rev ? (T_LEN - 4 - flowA) : flowA;
        const int addrB = rev ? (T_LEN - 4 - flowB) : flowB;
        float4 va = *(const float4*)(x + addrA);
        float4 vb = *(const float4*)(x + addrB);

        float a0, a1, a2, a3, b0, b1, b2, b3;
        UNPACK(va, a0, a1, a2, a3);
        UNPACK(vb, b0, b1, b2, b3);

        const float cr = (lane == 0) ? C.x : 0.f;
        const float ci = (lane == 0) ? C.y : 0.f;
        float Av0r,Av0i,Av1r,Av1i,Av2r,Av2i,Av3r,Av3i;
        LOCAL4(a0,a1,a2,a3, cr,ci, Av0r,Av0i,Av1r,Av1i,Av2r,Av2i,Av3r,Av3i);
        float Bv0r,Bv0i,Bv1r,Bv1i,Bv2r,Bv2i,Bv3r,Bv3i;
        LOCAL4(b0,b1,b2,b3, 0.f,0.f, Bv0r,Bv0i,Bv1r,Bv1i,Bv2r,Bv2i,Bv3r,Bv3i);

        float Air = Av3r, Aii = Av3i;
        float Bir = Bv3r, Bii = Bv3i;
        KS_SCAN(Air, Aii);
        KS_SCAN(Bir, Bii);

        float Apr = __shfl_up_sync(FULL, Air, 1);
        float Api = __shfl_up_sync(FULL, Aii, 1);
        if (lane == 0) { Apr = 0.f; Api = 0.f; }
        EMIT(addrA, Apr, Api, Av0r,Av0i,Av1r,Av1i,Av2r,Av2i, Air, Aii);

        const float CBr = __shfl_sync(FULL, Air, 31);
        const float CBi = __shfl_sync(FULL, Aii, 31);

        const float Bxr = __shfl_sync(FULL, Bir, srcB);
        const float Bxi = __shfl_sync(FULL, Bii, srcB);
        float Bpr, Bpi;
        if (lane == 0) { Bpr = CBr; Bpi = CBi; }
        else {
            Bpr = fmaf(E4j.x, CBr, fmaf(-E4j.y, CBi, Bxr));
            Bpi = fmaf(E4j.x, CBi, fmaf( E4j.y, CBr, Bxi));
        }
        float Bo3r = fmaf(E4.x, Bpr, fmaf(-E4.y, Bpi, Bv3r));
        float Bo3i = fmaf(E4.x, Bpi, fmaf( E4.y, Bpr, Bv3i));
        EMIT(addrB, Bpr, Bpi, Bv0r,Bv0i,Bv1r,Bv1i,Bv2r,Bv2i, Bo3r, Bo3i);

        C.x = fmaf(E128.x, CBr, fmaf(-E128.y, CBi, Bxr));
        C.y = fmaf(E128.x, CBi, fmaf( E128.y, CBr, Bxi));
    }

    // leftover tile 24: carry-injected single
    {
        const int flow = cb + 128 * (TILES - 1) + 4 * lane;
        const int addr = rev ? (T_LEN - 4 - flow) : flow;
        float4 va = *(const float4*)(x + addr);
        float a0, a1, a2, a3;
        UNPACK(va, a0, a1, a2, a3);
        const float cr = (lane == 0) ? C.x : 0.f;
        const float ci = (lane == 0) ? C.y : 0.f;
        float v0r,v0i,v1r,v1i,v2r,v2i,v3r,v3i;
        LOCAL4(a0,a1,a2,a3, cr,ci, v0r,v0i,v1r,v1i,v2r,v2i,v3r,v3i);
        float ir = v3r, ii = v3i;
        KS_SCAN(ir, ii);
        float pr = __shfl_up_sync(FULL, ir, 1);
        float pi = __shfl_up_sync(FULL, ii, 1);
        if (lane == 0) { pr = 0.f; pi = 0.f; }
        EMIT(addr, pr, pi, v0r,v0i,v1r,v1i,v2r,v2i, ir, ii);
    }
}

extern "C" void kernel_launch(void* const* d_in, const int* in_sizes, int n_in,
                              void* d_out, int out_size) {
    const float* audio = (const float*)d_in[0];
    const float* kre   = (const float*)d_in[1];
    const float* kim   = (const float*)d_in[2];
    float* out = (float*)d_out;
    dim3 grid(NBLK, 2);
    cspace_kernel<<<grid, 256>>>(audio, kre, kim, out);
}